// round 1
// baseline (speedup 1.0000x reference)
#include <cuda_runtime.h>
#include <math.h>

// Scratch: segment-start offsets for each ray (ray_indices is sorted).
// n_rays = 32768 in this problem; sized with margin. __device__ global per
// allocation rules.
#define MAX_RAYS 65536
__device__ int g_seg[MAX_RAYS + 1];

// ---------------------------------------------------------------------------
// Kernel A: build seg_start[] from sorted ray_indices.
// seg_start[r] = first sample index with ray_indices[i] == r (searchsorted).
// seg_start[n_rays] = S. Handles (unlikely) empty rays via the gap loop.
// ---------------------------------------------------------------------------
__global__ void seg_boundary_kernel(const int* __restrict__ ri, int S, int n_rays) {
    int i = blockIdx.x * blockDim.x + threadIdx.x;
    if (i >= S) return;
    int r = ri[i];
    int rp = (i == 0) ? -1 : ri[i - 1];
    for (int rr = rp + 1; rr <= r; ++rr) g_seg[rr] = i;
    if (i == S - 1) {
        for (int rr = r + 1; rr <= n_rays; ++rr) g_seg[rr] = S;
    }
}

// ---------------------------------------------------------------------------
// Kernel B: one warp per ray.
// Each lane handles one sample per 32-sample chunk:
//   MLP: h = relu(pos @ W1 + b1) [64]; sigma = softplus(h @ W2 + b2)
//   s = sigma * dt; segmented exclusive cumsum via warp shfl scan + carry
//   w = exp(-(carry+excl)) * (1 - exp(-s))   [== trans * alpha, no cancellation]
//   accumulate opacity and weighted depth; reduce across warp at end.
// Weights held in shared: float4 {W1[0][j], W1[1][j], W1[2][j], b1[j]} + W2[j].
// ---------------------------------------------------------------------------
__global__ void __launch_bounds__(256) render_kernel(
    const float* __restrict__ rays_o,
    const float* __restrict__ rays_d,
    const float* __restrict__ W1,
    const float* __restrict__ b1,
    const float* __restrict__ W2,
    const float* __restrict__ b2,
    const float* __restrict__ t_starts,
    const float* __restrict__ t_ends,
    float* __restrict__ out,
    int n_rays)
{
    __shared__ float4 wp[64];
    __shared__ float  w2s[64];
    for (int j = threadIdx.x; j < 64; j += blockDim.x) {
        wp[j]  = make_float4(W1[j], W1[64 + j], W1[128 + j], b1[j]);
        w2s[j] = W2[j];
    }
    __syncthreads();
    const float b2v = __ldg(b2);

    const int warp_id = (blockIdx.x * blockDim.x + threadIdx.x) >> 5;
    const int lane    = threadIdx.x & 31;
    if (warp_id >= n_rays) return;   // uniform per warp
    const int r = warp_id;

    const int start = g_seg[r];
    const int end   = g_seg[r + 1];

    const float ox = __ldg(&rays_o[3 * r    ]);
    const float oy = __ldg(&rays_o[3 * r + 1]);
    const float oz = __ldg(&rays_o[3 * r + 2]);
    const float dx = __ldg(&rays_d[3 * r    ]);
    const float dy = __ldg(&rays_d[3 * r + 1]);
    const float dz = __ldg(&rays_d[3 * r + 2]);

    float carry = 0.f;          // running within-ray cumsum of s
    float opac  = 0.f;          // per-lane partial opacity
    float dnum  = 0.f;          // per-lane partial weighted-depth

    for (int i0 = start; i0 < end; i0 += 32) {
        const int  i     = i0 + lane;
        const bool valid = (i < end);

        float s = 0.f, tm = 0.f;
        if (valid) {
            const float ts = t_starts[i];
            const float te = t_ends[i];
            tm = 0.5f * (ts + te);
            const float dt = te - ts;

            const float px = fmaf(dx, tm, ox);
            const float py = fmaf(dy, tm, oy);
            const float pz = fmaf(dz, tm, oz);

            float acc = b2v;
            #pragma unroll
            for (int j = 0; j < 64; ++j) {
                const float4 w = wp[j];
                float h = fmaf(px, w.x, fmaf(py, w.y, fmaf(pz, w.z, w.w)));
                h = fmaxf(h, 0.f);
                acc = fmaf(h, w2s[j], acc);
            }
            // softplus(acc) = log1p(exp(acc)); acc is bounded well below overflow
            float sp = (acc > 80.f) ? acc : log1pf(__expf(acc));
            s = sp * dt;
        }

        // warp-inclusive scan of s (all lanes participate)
        float incl = s;
        #pragma unroll
        for (int off = 1; off < 32; off <<= 1) {
            float v = __shfl_up_sync(0xffffffffu, incl, off);
            if (lane >= off) incl += v;
        }
        const float excl = incl - s;

        if (valid) {
            // trans * alpha = exp(-(carry+excl)) * (1 - exp(-s))
            const float w = __expf(-(carry + excl)) * (-expm1f(-s));
            opac += w;
            dnum  = fmaf(w, tm, dnum);
        }
        carry += __shfl_sync(0xffffffffu, incl, 31);
    }

    // warp reduction
    #pragma unroll
    for (int off = 16; off; off >>= 1) {
        opac += __shfl_xor_sync(0xffffffffu, opac, off);
        dnum += __shfl_xor_sync(0xffffffffu, dnum, off);
    }

    if (lane == 0) {
        const float depth = dnum / fmaxf(opac, 1.17549435e-38f); // clip(opac, tiny)
        out[2 * r    ] = opac;
        out[2 * r + 1] = depth;
    }
}

// ---------------------------------------------------------------------------
// kernel_launch: inputs per metadata order:
// [0] rays_o [N,3] f32, [1] rays_d [N,3] f32, [2] W1 [3,64] f32, [3] b1 [64],
// [4] W2 [64,1], [5] b2 [1], [6] t_starts [S], [7] t_ends [S],
// [8] ray_indices [S] i32, [9] n_rays (scalar)
// ---------------------------------------------------------------------------
extern "C" void kernel_launch(void* const* d_in, const int* in_sizes, int n_in,
                              void* d_out, int out_size) {
    const float* rays_o      = (const float*)d_in[0];
    const float* rays_d      = (const float*)d_in[1];
    const float* W1          = (const float*)d_in[2];
    const float* b1          = (const float*)d_in[3];
    const float* W2          = (const float*)d_in[4];
    const float* b2          = (const float*)d_in[5];
    const float* t_starts    = (const float*)d_in[6];
    const float* t_ends      = (const float*)d_in[7];
    const int*   ray_indices = (const int*)d_in[8];

    const int S      = in_sizes[6];
    const int n_rays = in_sizes[0] / 3;

    float* out = (float*)d_out;

    seg_boundary_kernel<<<(S + 255) / 256, 256>>>(ray_indices, S, n_rays);

    const int warps_per_block = 8;
    const int blocks = (n_rays + warps_per_block - 1) / warps_per_block;
    render_kernel<<<blocks, warps_per_block * 32>>>(
        rays_o, rays_d, W1, b1, W2, b2, t_starts, t_ends, out, n_rays);
}

// round 2
// speedup vs baseline: 1.5130x; 1.5130x over previous
#include <cuda_runtime.h>
#include <math.h>

#define MAX_RAYS 65536
__device__ int g_seg[MAX_RAYS + 1];

typedef unsigned long long ull;

// ---- packed f32x2 helpers (Blackwell) -------------------------------------
__device__ __forceinline__ ull f2fma(ull a, ull b, ull c) {
    ull d;
    asm("fma.rn.f32x2 %0, %1, %2, %3;" : "=l"(d) : "l"(a), "l"(b), "l"(c));
    return d;
}
__device__ __forceinline__ ull f2add(ull a, ull b) {
    ull d;
    asm("add.rn.f32x2 %0, %1, %2;" : "=l"(d) : "l"(a), "l"(b));
    return d;
}
__device__ __forceinline__ ull f2pack(float lo, float hi) {
    ull d;
    asm("mov.b64 %0, {%1, %2};" : "=l"(d) : "f"(lo), "f"(hi));
    return d;
}
__device__ __forceinline__ void f2unpack(ull v, float& lo, float& hi) {
    asm("mov.b64 {%0, %1}, %2;" : "=f"(lo), "=f"(hi) : "l"(v));
}

// ---------------------------------------------------------------------------
// Kernel A: segment starts from sorted ray_indices (searchsorted).
// ---------------------------------------------------------------------------
__global__ void seg_boundary_kernel(const int* __restrict__ ri, int S, int n_rays) {
    int i = blockIdx.x * blockDim.x + threadIdx.x;
    if (i >= S) return;
    int r = ri[i];
    int rp = (i == 0) ? -1 : ri[i - 1];
    for (int rr = rp + 1; rr <= r; ++rr) g_seg[rr] = i;
    if (i == S - 1) {
        for (int rr = r + 1; rr <= n_rays; ++rr) g_seg[rr] = S;
    }
}

// ---------------------------------------------------------------------------
// Kernel B: one warp per ray; f32x2-packed MLP (2 hidden units/instr).
// Shared layout per pair p (units 2p, 2p+1):
//   sA[p] = {wx2, wy2}   (two packed f32x2 in a 16B LDS.128)
//   sB[p] = {wz2, b1_2}
//   sC[p] =  w2_2 * 0.5  (0.5 folded in: relu(x) = 0.5*(x+|x|))
// ---------------------------------------------------------------------------
__global__ void __launch_bounds__(256, 2) render_kernel(
    const float* __restrict__ rays_o,
    const float* __restrict__ rays_d,
    const float* __restrict__ W1,
    const float* __restrict__ b1,
    const float* __restrict__ W2,
    const float* __restrict__ b2,
    const float* __restrict__ t_starts,
    const float* __restrict__ t_ends,
    float* __restrict__ out,
    int n_rays)
{
    __shared__ ulonglong2 sA[32];
    __shared__ ulonglong2 sB[32];
    __shared__ ull        sC[32];

    if (threadIdx.x < 32) {
        const int p = threadIdx.x;
        const int j = 2 * p;
        ulonglong2 A, B;
        A.x = f2pack(W1[j],       W1[j + 1]);        // W1 row 0 (x)
        A.y = f2pack(W1[64 + j],  W1[64 + j + 1]);   // W1 row 1 (y)
        B.x = f2pack(W1[128 + j], W1[128 + j + 1]);  // W1 row 2 (z)
        B.y = f2pack(b1[j],       b1[j + 1]);        // bias
        sA[p] = A;
        sB[p] = B;
        sC[p] = f2pack(0.5f * W2[j], 0.5f * W2[j + 1]);
    }
    __syncthreads();
    const float b2v = __ldg(b2);

    const int warp_id = (blockIdx.x * blockDim.x + threadIdx.x) >> 5;
    const int lane    = threadIdx.x & 31;
    if (warp_id >= n_rays) return;
    const int r = warp_id;

    const int start = g_seg[r];
    const int end   = g_seg[r + 1];

    const float ox = __ldg(&rays_o[3 * r    ]);
    const float oy = __ldg(&rays_o[3 * r + 1]);
    const float oz = __ldg(&rays_o[3 * r + 2]);
    const float dx = __ldg(&rays_d[3 * r    ]);
    const float dy = __ldg(&rays_d[3 * r + 1]);
    const float dz = __ldg(&rays_d[3 * r + 2]);

    float carry = 0.f;
    float opac  = 0.f;
    float dnum  = 0.f;

    for (int i0 = start; i0 < end; i0 += 32) {
        const int  i     = i0 + lane;
        const bool valid = (i < end);

        float s = 0.f, tm = 0.f;
        if (valid) {
            const float ts = t_starts[i];
            const float te = t_ends[i];
            tm = 0.5f * (ts + te);
            const float dt = te - ts;

            const float px = fmaf(dx, tm, ox);
            const float py = fmaf(dy, tm, oy);
            const float pz = fmaf(dz, tm, oz);

            const ull px2 = f2pack(px, px);
            const ull py2 = f2pack(py, py);
            const ull pz2 = f2pack(pz, pz);

            ull acc0 = 0ull, acc1 = 0ull;   // packed {0.f, 0.f}
            #pragma unroll 8
            for (int p = 0; p < 32; p += 2) {
                {
                    const ulonglong2 A = sA[p];
                    const ulonglong2 B = sB[p];
                    const ull        C = sC[p];
                    ull h = f2fma(pz2, B.x, B.y);
                    h = f2fma(py2, A.y, h);
                    h = f2fma(px2, A.x, h);
                    const ull a = h & 0x7FFFFFFF7FFFFFFFULL;  // |h| per half
                    h = f2add(h, a);                           // 2*relu(h)
                    acc0 = f2fma(h, C, acc0);                  // += relu*w2
                }
                {
                    const ulonglong2 A = sA[p + 1];
                    const ulonglong2 B = sB[p + 1];
                    const ull        C = sC[p + 1];
                    ull h = f2fma(pz2, B.x, B.y);
                    h = f2fma(py2, A.y, h);
                    h = f2fma(px2, A.x, h);
                    const ull a = h & 0x7FFFFFFF7FFFFFFFULL;
                    h = f2add(h, a);
                    acc1 = f2fma(h, C, acc1);
                }
            }
            float alo, ahi;
            f2unpack(f2add(acc0, acc1), alo, ahi);
            const float acc = b2v + alo + ahi;

            // softplus(x) = max(x,0) + log(1 + exp(-|x|)), branch-free/fast
            const float e  = __expf(-fabsf(acc));
            const float sp = fmaxf(acc, 0.f) + __logf(1.f + e);
            s = sp * dt;
        }

        // warp-inclusive scan of s
        float incl = s;
        #pragma unroll
        for (int off = 1; off < 32; off <<= 1) {
            float v = __shfl_up_sync(0xffffffffu, incl, off);
            if (lane >= off) incl += v;
        }
        const float excl = incl - s;

        if (valid) {
            const float w = __expf(-(carry + excl)) * (-expm1f(-s));
            opac += w;
            dnum  = fmaf(w, tm, dnum);
        }
        carry += __shfl_sync(0xffffffffu, incl, 31);
    }

    #pragma unroll
    for (int off = 16; off; off >>= 1) {
        opac += __shfl_xor_sync(0xffffffffu, opac, off);
        dnum += __shfl_xor_sync(0xffffffffu, dnum, off);
    }

    if (lane == 0) {
        const float depth = dnum / fmaxf(opac, 1.17549435e-38f);
        out[2 * r    ] = opac;
        out[2 * r + 1] = depth;
    }
}

extern "C" void kernel_launch(void* const* d_in, const int* in_sizes, int n_in,
                              void* d_out, int out_size) {
    const float* rays_o      = (const float*)d_in[0];
    const float* rays_d      = (const float*)d_in[1];
    const float* W1          = (const float*)d_in[2];
    const float* b1          = (const float*)d_in[3];
    const float* W2          = (const float*)d_in[4];
    const float* b2          = (const float*)d_in[5];
    const float* t_starts    = (const float*)d_in[6];
    const float* t_ends      = (const float*)d_in[7];
    const int*   ray_indices = (const int*)d_in[8];

    const int S      = in_sizes[6];
    const int n_rays = in_sizes[0] / 3;

    float* out = (float*)d_out;

    seg_boundary_kernel<<<(S + 255) / 256, 256>>>(ray_indices, S, n_rays);

    const int warps_per_block = 8;
    const int blocks = (n_rays + warps_per_block - 1) / warps_per_block;
    render_kernel<<<blocks, warps_per_block * 32>>>(
        rays_o, rays_d, W1, b1, W2, b2, t_starts, t_ends, out, n_rays);
}